// round 11
// baseline (speedup 1.0000x reference)
#include <cuda_runtime.h>
#include <cstdint>
#include <cstddef>

#define TL 512
#define NB 2048
#define NB16 (NB*16)
#define FULL 0xffffffffu

// scratch: hproj_seq, T*B*16 floats = 64 MiB
__device__ float g_hproj[(size_t)TL * NB * 16];

__device__ __forceinline__ float sigf(float x){
  return __fdividef(1.f, 1.f + __expf(-x));
}
__device__ __forceinline__ float tanh_fast(float x){
  return __fdividef(2.f, 1.f + __expf(-2.f * x)) - 1.f;
}

// ---- packed f32x2 helpers ----
__device__ __forceinline__ uint64_t pk2(float lo, float hi){
  uint64_t r; asm("mov.b64 %0, {%1, %2};" : "=l"(r) : "f"(lo), "f"(hi)); return r;
}
__device__ __forceinline__ uint64_t fma2(uint64_t a, uint64_t b, uint64_t c){
  uint64_t d; asm("fma.rn.f32x2 %0, %1, %2, %3;" : "=l"(d) : "l"(a), "l"(b), "l"(c));
  return d;
}
__device__ __forceinline__ float dot16p(const uint64_t w[8], const uint64_t v[8]){
  const uint64_t z = 0;
  uint64_t a0 = fma2(w[0], v[0], z);
  uint64_t a1 = fma2(w[1], v[1], z);
  a0 = fma2(w[2], v[2], a0);
  a1 = fma2(w[3], v[3], a1);
  a0 = fma2(w[4], v[4], a0);
  a1 = fma2(w[5], v[5], a1);
  a0 = fma2(w[6], v[6], a0);
  a1 = fma2(w[7], v[7], a1);
  uint64_t s; asm("add.rn.f32x2 %0, %1, %2;" : "=l"(s) : "l"(a0), "l"(a1));
  float lo, hi; asm("mov.b64 {%0, %1}, %2;" : "=f"(lo), "=f"(hi) : "l"(s));
  return lo + hi;
}
__device__ __forceinline__ void ldv8p(const float* p, uint64_t v[8]){
  #pragma unroll
  for (int i = 0; i < 4; i++){
    ulonglong2 q = reinterpret_cast<const ulonglong2*>(p)[i];
    v[2*i] = q.x; v[2*i+1] = q.y;
  }
}

// ============================================================================
// Phase 1: backward LSTM scan + fused hproj (identical to R5 best).
// ============================================================================
__global__ __launch_bounds__(64)
void lstm_bwd_kernel(const float* __restrict__ x,
                     const float* __restrict__ Wih,
                     const float* __restrict__ Whh,
                     const float* __restrict__ bih,
                     const float* __restrict__ bhh,
                     const float* __restrict__ cW1,
                     const float* __restrict__ cb1)
{
  const int l = threadIdx.x & 31;
  const int w = threadIdx.x >> 5;
  const int b = blockIdx.x * 2 + w;
  const int lo = l & 15;

  __shared__ __align__(16) float sH[2][16];
  float* hbuf = sH[w];

  const int r0 = l, r1 = l + 32;
  uint64_t w0[8], w1[8], wHp[8];
  #pragma unroll
  for (int j = 0; j < 8; j++){
    w0[j]  = pk2(Whh[r0*16 + 2*j], Whh[r0*16 + 2*j + 1]);
    w1[j]  = pk2(Whh[r1*16 + 2*j], Whh[r1*16 + 2*j + 1]);
    wHp[j] = pk2(cW1[lo*32 + 2*j], cW1[lo*32 + 2*j + 1]);
  }
  const float wx0 = Wih[r0], wx1 = Wih[r1];
  const float b0 = bih[r0] + bhh[r0];
  const float b1 = bih[r1] + bhh[r1];
  const float bHp = cb1[lo];

  if (l < 16) hbuf[l] = 0.f;
  float c = 0.f;
  __syncwarp();

  const float* xb = x + b;
  float* hpout = g_hproj + (size_t)b * 16 + lo;

  float xt = __ldg(xb + (size_t)(TL-1) * NB);

  for (int t = TL - 1; t >= 0; --t){
    float xn = 0.f;
    if (t > 0) xn = __ldg(xb + (size_t)(t-1) * NB);

    uint64_t hv[8]; ldv8p(hbuf, hv);

    float hp = bHp + dot16p(wHp, hv);
    if (l < 16 && t != TL - 1)
      hpout[(size_t)(t+1) * NB16] = hp;

    float a0 = fmaf(xt, wx0, b0) + dot16p(w0, hv);
    float a1 = fmaf(xt, wx1, b1) + dot16p(w1, hv);

    float p, q = 0.f;
    if (l < 16) { p = sigf(a0) * tanh_fast(a1); }
    else        { p = sigf(a0); q = sigf(a1); }
    float pf = __shfl_xor_sync(FULL, p, 16);
    float qo = __shfl_xor_sync(FULL, q, 16);
    __syncwarp();
    if (l < 16){
      c = fmaf(pf, c, p);
      float hn = qo * tanh_fast(c);
      hbuf[l] = hn;
    }
    __syncwarp();
    xt = xn;
  }

  {
    uint64_t hv[8]; ldv8p(hbuf, hv);
    float hp = bHp + dot16p(wHp, hv);
    if (l < 16) hpout[0] = hp;
  }
}

// ============================================================================
// Phase 2: FUSED DKF recurrence + decoder + transition. One warp per batch.
// Lane roles (lo = l&15):
//   stage2 dot1: low = layer-A row lo (hproj + cW1z@z_prev); high = tr1 row lo
//   stage2 dot2: dec1 row lo (dup halves), input z_prev = z of PREVIOUS step
//                -> dec output deferred one step
//   stage4 dot1: tr2 row l (all lanes) -> out[34+l]
//   stage4 dot2: low = fusedM row lo @ a1 -> e1 ; high = dec2 row (l&1) @ d1
//   stage6     : e2 = enc2 row l @ e1 -> out[2+l]; sample z
// 3 syncwarps/step (unchanged from R5). No z_seq scratch.
// ============================================================================
__global__ __launch_bounds__(64)
void dkf_fused_kernel(const float* __restrict__ eps,
                      const float* __restrict__ cW1,
                      const float* __restrict__ cW2, const float* __restrict__ cb2,
                      const float* __restrict__ eW1, const float* __restrict__ eb1,
                      const float* __restrict__ eW2, const float* __restrict__ eb2,
                      const float* __restrict__ dW1, const float* __restrict__ db1,
                      const float* __restrict__ dW2, const float* __restrict__ db2,
                      const float* __restrict__ tW1, const float* __restrict__ tb1,
                      const float* __restrict__ tW2, const float* __restrict__ tb2,
                      float* __restrict__ out)
{
  const int l = threadIdx.x & 31;
  const int w = threadIdx.x >> 5;
  const int b = blockIdx.x * 2 + w;
  const int lo = l & 15;
  const bool low = (l < 16);

  __shared__ __align__(16) float sm[2][80];
  float* SA = &sm[w][0];    // a1 (16)
  float* ST = &sm[w][16];   // t1 (16)
  float* SD = &sm[w][32];   // d1 (16)
  float* SC = &sm[w][48];   // e1 (16)
  float* SZ = &sm[w][64];   // z  (16)

  // ---- per-lane weight rows ----
  // w1: low = cW1 z-cols row lo ; high = tW1 row lo
  uint64_t w1r[8];
  #pragma unroll
  for (int j = 0; j < 8; j++){
    const float* src = low ? (cW1 + lo*32 + 16) : (tW1 + lo*16);
    w1r[j] = pk2(src[2*j], src[2*j+1]);
  }
  // w2: dec1 row lo (dup halves)
  uint64_t w2r[8];
  #pragma unroll
  for (int j = 0; j < 8; j++)
    w2r[j] = pk2(dW1[lo*16 + 2*j], dW1[lo*16 + 2*j + 1]);
  // w3: tr2 row l
  uint64_t w3r[8];
  #pragma unroll
  for (int j = 0; j < 8; j++)
    w3r[j] = pk2(tW2[l*16 + 2*j], tW2[l*16 + 2*j + 1]);
  // w4: low = fused M row lo (eW1@cW2); high = dW2 row (l&1)
  uint64_t w4r[8];
  float bM = 0.f;
  if (low){
    float e1w[8];
    #pragma unroll
    for (int k = 0; k < 8; k++) e1w[k] = eW1[lo*8 + k];
    #pragma unroll
    for (int cc = 0; cc < 8; cc++){
      float ax = 0.f, ay = 0.f;
      #pragma unroll
      for (int k = 0; k < 8; k++){
        ax = fmaf(e1w[k], cW2[k*16 + 2*cc],     ax);
        ay = fmaf(e1w[k], cW2[k*16 + 2*cc + 1], ay);
      }
      w4r[cc] = pk2(ax, ay);
    }
    bM = eb1[lo];
    #pragma unroll
    for (int k = 0; k < 8; k++) bM = fmaf(e1w[k], cb2[k], bM);
  } else {
    #pragma unroll
    for (int j = 0; j < 8; j++)
      w4r[j] = pk2(dW2[(l&1)*16 + 2*j], dW2[(l&1)*16 + 2*j + 1]);
  }
  // wD: enc2 row l
  uint64_t wDr[8];
  #pragma unroll
  for (int j = 0; j < 8; j++)
    wDr[j] = pk2(eW2[l*16 + 2*j], eW2[l*16 + 2*j + 1]);

  const float bT1r = tb1[lo];
  const float bD1r = db1[lo];
  const float bT2r = tb2[l];
  const float bD2r = db2[l & 1];
  const float bDr  = eb2[l];

  if (low) SZ[lo] = 0.f;      // z0
  __syncwarp();

  const float* hpp = g_hproj + (size_t)b * 16 + lo;
  const float* epp = eps     + (size_t)b * 16 + lo;
  float*       outp = out    + (size_t)b * 66;

  // ---- 4-deep prefetch ring ----
  float hp0 = __ldg(hpp);
  float hp1 = __ldg(hpp + (size_t)1 * NB16);
  float hp2 = __ldg(hpp + (size_t)2 * NB16);
  float hp3 = __ldg(hpp + (size_t)3 * NB16);
  float ep0 = __ldg(epp);
  float ep1 = __ldg(epp + (size_t)1 * NB16);
  float ep2 = __ldg(epp + (size_t)2 * NB16);
  float ep3 = __ldg(epp + (size_t)3 * NB16);

  const float* avdv_src = low ? SA : SD;   // stage-4 dot2 operand per half

  #define DKF_STEP(T, HPV, EPSV)                                          \
  {                                                                       \
    /* stage 2: A|tr1 + dec1, all from z_prev */                          \
    uint64_t zv[8]; ldv8p(SZ, zv);                                        \
    float base1 = low ? (HPV) : bT1r;                                     \
    float v1 = tanh_fast(base1 + dot16p(w1r, zv));   /* a1 | t1 */        \
    float d1 = tanh_fast(bD1r + dot16p(w2r, zv));    /* dec1 (prev z) */  \
    if (low){ SA[lo] = v1; SD[lo] = d1; } else { ST[lo] = v1; }           \
    __syncwarp();                                                         \
    /* stage 4: tr2 + (e1 | dec2) */                                      \
    uint64_t tv[8]; ldv8p(ST, tv);                                        \
    float r2 = bT2r + dot16p(w3r, tv);                                    \
    outp[34 + l] = r2;                                                    \
    uint64_t av[8]; ldv8p(avdv_src, av);                                  \
    float base4 = low ? bM : bD2r;                                        \
    float v4 = base4 + dot16p(w4r, av);              /* e1pre | dx */     \
    if (low) SC[lo] = tanh_fast(v4);                                      \
    else if (((unsigned)(l - 16)) < 2u && (T) > 0)                        \
      (outp - (size_t)NB * 66)[l - 16] = v4;         /* mu_x/logvar_x */  \
    __syncwarp();                                                         \
    /* stage 6: enc2 + sample */                                          \
    uint64_t ev[8]; ldv8p(SC, ev);                                        \
    float e2 = bDr + dot16p(wDr, ev);                                     \
    outp[2 + l] = e2;                                                     \
    float lvz = __shfl_xor_sync(FULL, e2, 16);                            \
    float znew = fmaf((EPSV), __expf(0.5f * lvz), e2);                    \
    if (low) SZ[lo] = znew;                                               \
    __syncwarp();                                                         \
    outp += (size_t)NB * 66;                                              \
  }

  #pragma unroll 1
  for (int t = 0; t < TL; t += 4){
    int t4 = t + 4; if (t4 > TL-1) t4 = TL-1;
    int t5 = t + 5; if (t5 > TL-1) t5 = TL-1;
    int t6 = t + 6; if (t6 > TL-1) t6 = TL-1;
    int t7 = t + 7; if (t7 > TL-1) t7 = TL-1;

    float hpa = __ldg(hpp + (size_t)t4 * NB16);
    float epa = __ldg(epp + (size_t)t4 * NB16);
    DKF_STEP(t + 0, hp0, ep0);
    hp0 = hpa; ep0 = epa;

    float hpb = __ldg(hpp + (size_t)t5 * NB16);
    float epb = __ldg(epp + (size_t)t5 * NB16);
    DKF_STEP(t + 1, hp1, ep1);
    hp1 = hpb; ep1 = epb;

    float hpc = __ldg(hpp + (size_t)t6 * NB16);
    float epc = __ldg(epp + (size_t)t6 * NB16);
    DKF_STEP(t + 2, hp2, ep2);
    hp2 = hpc; ep2 = epc;

    float hpd = __ldg(hpp + (size_t)t7 * NB16);
    float epd = __ldg(epp + (size_t)t7 * NB16);
    DKF_STEP(t + 3, hp3, ep3);
    hp3 = hpd; ep3 = epd;
  }
  #undef DKF_STEP

  // epilogue: decoder for z_{TL-1} (outp now = base + TL*NB*66)
  {
    uint64_t zv[8]; ldv8p(SZ, zv);
    float d1 = tanh_fast(bD1r + dot16p(w2r, zv));
    if (low) SD[lo] = d1;
    __syncwarp();
    uint64_t dv[8]; ldv8p(SD, dv);
    float dx = bD2r + dot16p(w4r, dv);     // valid on high lanes
    if (((unsigned)(l - 16)) < 2u)
      (outp - (size_t)NB * 66)[l - 16] = dx;
  }
}

extern "C" void kernel_launch(void* const* d_in, const int* in_sizes, int n_in,
                              void* d_out, int out_size)
{
  const float* x   = (const float*)d_in[0];
  const float* eps = (const float*)d_in[1];
  const float* Wih = (const float*)d_in[2];
  const float* Whh = (const float*)d_in[3];
  const float* bih = (const float*)d_in[4];
  const float* bhh = (const float*)d_in[5];
  const float* cW1 = (const float*)d_in[6];
  const float* cb1 = (const float*)d_in[7];
  const float* cW2 = (const float*)d_in[8];
  const float* cb2 = (const float*)d_in[9];
  const float* eW1 = (const float*)d_in[10];
  const float* eb1 = (const float*)d_in[11];
  const float* eW2 = (const float*)d_in[12];
  const float* eb2 = (const float*)d_in[13];
  const float* dW1 = (const float*)d_in[14];
  const float* db1 = (const float*)d_in[15];
  const float* dW2 = (const float*)d_in[16];
  const float* db2 = (const float*)d_in[17];
  const float* tW1 = (const float*)d_in[18];
  const float* tb1 = (const float*)d_in[19];
  const float* tW2 = (const float*)d_in[20];
  const float* tb2 = (const float*)d_in[21];
  float* out = (float*)d_out;

  lstm_bwd_kernel<<<NB/2, 64>>>(x, Wih, Whh, bih, bhh, cW1, cb1);
  dkf_fused_kernel<<<NB/2, 64>>>(eps, cW1, cW2, cb2, eW1, eb1, eW2, eb2,
                                 dW1, db1, dW2, db2, tW1, tb1, tW2, tb2, out);
}

// round 12
// speedup vs baseline: 1.0019x; 1.0019x over previous
#include <cuda_runtime.h>
#include <cstdint>
#include <cstddef>

#define TL 512
#define NB 2048
#define NB16 (NB*16)
#define FULL 0xffffffffu

// scratch: hproj_seq, T*B*16 floats = 64 MiB
__device__ float g_hproj[(size_t)TL * NB * 16];

__device__ __forceinline__ float sigf(float x){
  return __fdividef(1.f, 1.f + __expf(-x));
}
__device__ __forceinline__ float tanh_fast(float x){
  return __fdividef(2.f, 1.f + __expf(-2.f * x)) - 1.f;
}

// ---- packed f32x2 helpers ----
__device__ __forceinline__ uint64_t pk2(float lo, float hi){
  uint64_t r; asm("mov.b64 %0, {%1, %2};" : "=l"(r) : "f"(lo), "f"(hi)); return r;
}
__device__ __forceinline__ uint64_t fma2(uint64_t a, uint64_t b, uint64_t c){
  uint64_t d; asm("fma.rn.f32x2 %0, %1, %2, %3;" : "=l"(d) : "l"(a), "l"(b), "l"(c));
  return d;
}
__device__ __forceinline__ float dot16p(const uint64_t w[8], const uint64_t v[8]){
  const uint64_t z = 0;
  uint64_t a0 = fma2(w[0], v[0], z);
  uint64_t a1 = fma2(w[1], v[1], z);
  a0 = fma2(w[2], v[2], a0);
  a1 = fma2(w[3], v[3], a1);
  a0 = fma2(w[4], v[4], a0);
  a1 = fma2(w[5], v[5], a1);
  a0 = fma2(w[6], v[6], a0);
  a1 = fma2(w[7], v[7], a1);
  uint64_t s; asm("add.rn.f32x2 %0, %1, %2;" : "=l"(s) : "l"(a0), "l"(a1));
  float lo, hi; asm("mov.b64 {%0, %1}, %2;" : "=f"(lo), "=f"(hi) : "l"(s));
  return lo + hi;
}
__device__ __forceinline__ void ldv8p(const float* p, uint64_t v[8]){
  #pragma unroll
  for (int i = 0; i < 4; i++){
    ulonglong2 q = reinterpret_cast<const ulonglong2*>(p)[i];
    v[2*i] = q.x; v[2*i+1] = q.y;
  }
}

// ============================================================================
// Phase 1: backward LSTM scan + fused hproj (R5 best, unchanged).
// ============================================================================
__global__ __launch_bounds__(64)
void lstm_bwd_kernel(const float* __restrict__ x,
                     const float* __restrict__ Wih,
                     const float* __restrict__ Whh,
                     const float* __restrict__ bih,
                     const float* __restrict__ bhh,
                     const float* __restrict__ cW1,
                     const float* __restrict__ cb1)
{
  const int l = threadIdx.x & 31;
  const int w = threadIdx.x >> 5;
  const int b = blockIdx.x * 2 + w;
  const int lo = l & 15;

  __shared__ __align__(16) float sH[2][16];
  float* hbuf = sH[w];

  const int r0 = l, r1 = l + 32;
  uint64_t w0[8], w1[8], wHp[8];
  #pragma unroll
  for (int j = 0; j < 8; j++){
    w0[j]  = pk2(Whh[r0*16 + 2*j], Whh[r0*16 + 2*j + 1]);
    w1[j]  = pk2(Whh[r1*16 + 2*j], Whh[r1*16 + 2*j + 1]);
    wHp[j] = pk2(cW1[lo*32 + 2*j], cW1[lo*32 + 2*j + 1]);
  }
  const float wx0 = Wih[r0], wx1 = Wih[r1];
  const float b0 = bih[r0] + bhh[r0];
  const float b1 = bih[r1] + bhh[r1];
  const float bHp = cb1[lo];

  if (l < 16) hbuf[l] = 0.f;
  float c = 0.f;
  __syncwarp();

  const float* xb = x + b;
  float* hpout = g_hproj + (size_t)b * 16 + lo;

  float xt = __ldg(xb + (size_t)(TL-1) * NB);

  for (int t = TL - 1; t >= 0; --t){
    float xn = 0.f;
    if (t > 0) xn = __ldg(xb + (size_t)(t-1) * NB);

    uint64_t hv[8]; ldv8p(hbuf, hv);

    float hp = bHp + dot16p(wHp, hv);
    if (l < 16 && t != TL - 1)
      hpout[(size_t)(t+1) * NB16] = hp;

    float a0 = fmaf(xt, wx0, b0) + dot16p(w0, hv);
    float a1 = fmaf(xt, wx1, b1) + dot16p(w1, hv);

    float p, q = 0.f;
    if (l < 16) { p = sigf(a0) * tanh_fast(a1); }
    else        { p = sigf(a0); q = sigf(a1); }
    float pf = __shfl_xor_sync(FULL, p, 16);
    float qo = __shfl_xor_sync(FULL, q, 16);
    __syncwarp();
    if (l < 16){
      c = fmaf(pf, c, p);
      float hn = qo * tanh_fast(c);
      hbuf[l] = hn;
    }
    __syncwarp();
    xt = xn;
  }

  {
    uint64_t hv[8]; ldv8p(hbuf, hv);
    float hp = bHp + dot16p(wHp, hv);
    if (l < 16) hpout[0] = hp;
  }
}

// ============================================================================
// Phase 2: FUSED DKF recurrence + decoder + transition (R11 structure).
// __launch_bounds__(64, 7) caps regs at 146 so the 1024-block grid fits in
// ONE wave (6.92 blocks/SM needed; 168 regs gave 6 -> two waves in R11).
// ============================================================================
__global__ __launch_bounds__(64, 7)
void dkf_fused_kernel(const float* __restrict__ eps,
                      const float* __restrict__ cW1,
                      const float* __restrict__ cW2, const float* __restrict__ cb2,
                      const float* __restrict__ eW1, const float* __restrict__ eb1,
                      const float* __restrict__ eW2, const float* __restrict__ eb2,
                      const float* __restrict__ dW1, const float* __restrict__ db1,
                      const float* __restrict__ dW2, const float* __restrict__ db2,
                      const float* __restrict__ tW1, const float* __restrict__ tb1,
                      const float* __restrict__ tW2, const float* __restrict__ tb2,
                      float* __restrict__ out)
{
  const int l = threadIdx.x & 31;
  const int w = threadIdx.x >> 5;
  const int b = blockIdx.x * 2 + w;
  const int lo = l & 15;
  const bool low = (l < 16);

  __shared__ __align__(16) float sm[2][80];
  float* SA = &sm[w][0];    // a1 (16)
  float* ST = &sm[w][16];   // t1 (16)
  float* SD = &sm[w][32];   // d1 (16)
  float* SC = &sm[w][48];   // e1 (16)
  float* SZ = &sm[w][64];   // z  (16)

  // ---- per-lane weight rows ----
  // w1: low = cW1 z-cols row lo ; high = tW1 row lo
  uint64_t w1r[8];
  #pragma unroll
  for (int j = 0; j < 8; j++){
    const float* src = low ? (cW1 + lo*32 + 16) : (tW1 + lo*16);
    w1r[j] = pk2(src[2*j], src[2*j+1]);
  }
  // w2: dec1 row lo (dup halves)
  uint64_t w2r[8];
  #pragma unroll
  for (int j = 0; j < 8; j++)
    w2r[j] = pk2(dW1[lo*16 + 2*j], dW1[lo*16 + 2*j + 1]);
  // w3: tr2 row l
  uint64_t w3r[8];
  #pragma unroll
  for (int j = 0; j < 8; j++)
    w3r[j] = pk2(tW2[l*16 + 2*j], tW2[l*16 + 2*j + 1]);
  // w4: low = fused M row lo (eW1@cW2); high = dW2 row (l&1)
  uint64_t w4r[8];
  float bM = 0.f;
  if (low){
    float e1w[8];
    #pragma unroll
    for (int k = 0; k < 8; k++) e1w[k] = eW1[lo*8 + k];
    #pragma unroll
    for (int cc = 0; cc < 8; cc++){
      float ax = 0.f, ay = 0.f;
      #pragma unroll
      for (int k = 0; k < 8; k++){
        ax = fmaf(e1w[k], cW2[k*16 + 2*cc],     ax);
        ay = fmaf(e1w[k], cW2[k*16 + 2*cc + 1], ay);
      }
      w4r[cc] = pk2(ax, ay);
    }
    bM = eb1[lo];
    #pragma unroll
    for (int k = 0; k < 8; k++) bM = fmaf(e1w[k], cb2[k], bM);
  } else {
    #pragma unroll
    for (int j = 0; j < 8; j++)
      w4r[j] = pk2(dW2[(l&1)*16 + 2*j], dW2[(l&1)*16 + 2*j + 1]);
  }
  // wD: enc2 row l
  uint64_t wDr[8];
  #pragma unroll
  for (int j = 0; j < 8; j++)
    wDr[j] = pk2(eW2[l*16 + 2*j], eW2[l*16 + 2*j + 1]);

  const float bT1r = tb1[lo];
  const float bD1r = db1[lo];
  const float bT2r = tb2[l];
  const float bD2r = db2[l & 1];
  const float bDr  = eb2[l];

  if (low) SZ[lo] = 0.f;      // z0
  __syncwarp();

  const float* hpp = g_hproj + (size_t)b * 16 + lo;
  const float* epp = eps     + (size_t)b * 16 + lo;
  float*       outp = out    + (size_t)b * 66;

  // ---- 4-deep prefetch ring ----
  float hp0 = __ldg(hpp);
  float hp1 = __ldg(hpp + (size_t)1 * NB16);
  float hp2 = __ldg(hpp + (size_t)2 * NB16);
  float hp3 = __ldg(hpp + (size_t)3 * NB16);
  float ep0 = __ldg(epp);
  float ep1 = __ldg(epp + (size_t)1 * NB16);
  float ep2 = __ldg(epp + (size_t)2 * NB16);
  float ep3 = __ldg(epp + (size_t)3 * NB16);

  #define DKF_STEP(T, HPV, EPSV)                                          \
  {                                                                       \
    /* stage 2: A|tr1 + dec1, all from z_prev */                          \
    uint64_t zv[8]; ldv8p(SZ, zv);                                        \
    float base1 = low ? (HPV) : bT1r;                                     \
    float v1 = tanh_fast(base1 + dot16p(w1r, zv));   /* a1 | t1 */        \
    float d1 = tanh_fast(bD1r + dot16p(w2r, zv));    /* dec1 (prev z) */  \
    if (low){ SA[lo] = v1; SD[lo] = d1; } else { ST[lo] = v1; }           \
    __syncwarp();                                                         \
    /* stage 4: tr2 + (e1 | dec2) */                                      \
    uint64_t tv[8]; ldv8p(ST, tv);                                        \
    float r2 = bT2r + dot16p(w3r, tv);                                    \
    outp[34 + l] = r2;                                                    \
    uint64_t av[8]; ldv8p(low ? SA : SD, av);                             \
    float base4 = low ? bM : bD2r;                                        \
    float v4 = base4 + dot16p(w4r, av);              /* e1pre | dx */     \
    if (low) SC[lo] = tanh_fast(v4);                                      \
    else if (((unsigned)(l - 16)) < 2u && (T) > 0)                        \
      (outp - (size_t)NB * 66)[l - 16] = v4;         /* mu_x/logvar_x */  \
    __syncwarp();                                                         \
    /* stage 6: enc2 + sample */                                          \
    uint64_t ev[8]; ldv8p(SC, ev);                                        \
    float e2 = bDr + dot16p(wDr, ev);                                     \
    outp[2 + l] = e2;                                                     \
    float lvz = __shfl_xor_sync(FULL, e2, 16);                            \
    float znew = fmaf((EPSV), __expf(0.5f * lvz), e2);                    \
    if (low) SZ[lo] = znew;                                               \
    __syncwarp();                                                         \
    outp += (size_t)NB * 66;                                              \
  }

  #pragma unroll 1
  for (int t = 0; t < TL; t += 4){
    int t4 = t + 4; if (t4 > TL-1) t4 = TL-1;
    int t5 = t + 5; if (t5 > TL-1) t5 = TL-1;
    int t6 = t + 6; if (t6 > TL-1) t6 = TL-1;
    int t7 = t + 7; if (t7 > TL-1) t7 = TL-1;

    float hpa = __ldg(hpp + (size_t)t4 * NB16);
    float epa = __ldg(epp + (size_t)t4 * NB16);
    DKF_STEP(t + 0, hp0, ep0);
    hp0 = hpa; ep0 = epa;

    float hpb = __ldg(hpp + (size_t)t5 * NB16);
    float epb = __ldg(epp + (size_t)t5 * NB16);
    DKF_STEP(t + 1, hp1, ep1);
    hp1 = hpb; ep1 = epb;

    float hpc = __ldg(hpp + (size_t)t6 * NB16);
    float epc = __ldg(epp + (size_t)t6 * NB16);
    DKF_STEP(t + 2, hp2, ep2);
    hp2 = hpc; ep2 = epc;

    float hpd = __ldg(hpp + (size_t)t7 * NB16);
    float epd = __ldg(epp + (size_t)t7 * NB16);
    DKF_STEP(t + 3, hp3, ep3);
    hp3 = hpd; ep3 = epd;
  }
  #undef DKF_STEP

  // epilogue: decoder for z_{TL-1} (outp now = base + TL*NB*66)
  {
    uint64_t zv[8]; ldv8p(SZ, zv);
    float d1 = tanh_fast(bD1r + dot16p(w2r, zv));
    if (low) SD[lo] = d1;
    __syncwarp();
    uint64_t dv[8]; ldv8p(SD, dv);
    float dx = bD2r + dot16p(w4r, dv);     // valid on high lanes
    if (((unsigned)(l - 16)) < 2u)
      (outp - (size_t)NB * 66)[l - 16] = dx;
  }
}

extern "C" void kernel_launch(void* const* d_in, const int* in_sizes, int n_in,
                              void* d_out, int out_size)
{
  const float* x   = (const float*)d_in[0];
  const float* eps = (const float*)d_in[1];
  const float* Wih = (const float*)d_in[2];
  const float* Whh = (const float*)d_in[3];
  const float* bih = (const float*)d_in[4];
  const float* bhh = (const float*)d_in[5];
  const float* cW1 = (const float*)d_in[6];
  const float* cb1 = (const float*)d_in[7];
  const float* cW2 = (const float*)d_in[8];
  const float* cb2 = (const float*)d_in[9];
  const float* eW1 = (const float*)d_in[10];
  const float* eb1 = (const float*)d_in[11];
  const float* eW2 = (const float*)d_in[12];
  const float* eb2 = (const float*)d_in[13];
  const float* dW1 = (const float*)d_in[14];
  const float* db1 = (const float*)d_in[15];
  const float* dW2 = (const float*)d_in[16];
  const float* db2 = (const float*)d_in[17];
  const float* tW1 = (const float*)d_in[18];
  const float* tb1 = (const float*)d_in[19];
  const float* tW2 = (const float*)d_in[20];
  const float* tb2 = (const float*)d_in[21];
  float* out = (float*)d_out;

  lstm_bwd_kernel<<<NB/2, 64>>>(x, Wih, Whh, bih, bhh, cW1, cb1);
  dkf_fused_kernel<<<NB/2, 64>>>(eps, cW1, cW2, cb2, eW1, eb1, eW2, eb2,
                                 dW1, db1, dW2, db2, tW1, tb1, tW2, tb2, out);
}

// round 13
// speedup vs baseline: 1.1657x; 1.1635x over previous
#include <cuda_runtime.h>
#include <cstdint>
#include <cstddef>

#define TL 512
#define NB 2048
#define NB16 (NB*16)
#define FULL 0xffffffffu

// scratch: hproj_seq, T*B*16 floats = 64 MiB
__device__ float g_hproj[(size_t)TL * NB * 16];

__device__ __forceinline__ float sigf(float x){
  return __fdividef(1.f, 1.f + __expf(-x));
}
__device__ __forceinline__ float tanh_fast(float x){
  return __fdividef(2.f, 1.f + __expf(-2.f * x)) - 1.f;
}

// ---- packed f32x2 helpers ----
__device__ __forceinline__ uint64_t pk2(float lo, float hi){
  uint64_t r; asm("mov.b64 %0, {%1, %2};" : "=l"(r) : "f"(lo), "f"(hi)); return r;
}
__device__ __forceinline__ uint64_t fma2(uint64_t a, uint64_t b, uint64_t c){
  uint64_t d; asm("fma.rn.f32x2 %0, %1, %2, %3;" : "=l"(d) : "l"(a), "l"(b), "l"(c));
  return d;
}
__device__ __forceinline__ float dot16p(const uint64_t w[8], const uint64_t v[8]){
  const uint64_t z = 0;
  uint64_t a0 = fma2(w[0], v[0], z);
  uint64_t a1 = fma2(w[1], v[1], z);
  a0 = fma2(w[2], v[2], a0);
  a1 = fma2(w[3], v[3], a1);
  a0 = fma2(w[4], v[4], a0);
  a1 = fma2(w[5], v[5], a1);
  a0 = fma2(w[6], v[6], a0);
  a1 = fma2(w[7], v[7], a1);
  uint64_t s; asm("add.rn.f32x2 %0, %1, %2;" : "=l"(s) : "l"(a0), "l"(a1));
  float lo, hi; asm("mov.b64 {%0, %1}, %2;" : "=f"(lo), "=f"(hi) : "l"(s));
  return lo + hi;
}
__device__ __forceinline__ void ldv8p(const float* p, uint64_t v[8]){
  #pragma unroll
  for (int i = 0; i < 4; i++){
    ulonglong2 q = reinterpret_cast<const ulonglong2*>(p)[i];
    v[2*i] = q.x; v[2*i+1] = q.y;
  }
}
__device__ __forceinline__ void unpk16(const uint64_t v[8], float s[16]){
  #pragma unroll
  for (int i = 0; i < 8; i++)
    asm("mov.b64 {%0, %1}, %2;" : "=f"(s[2*i]), "=f"(s[2*i+1]) : "l"(v[i]));
}
__device__ __forceinline__ void ldv16f(const float* p, float v[16]){
  #pragma unroll
  for (int i = 0; i < 4; i++){
    float4 q = reinterpret_cast<const float4*>(p)[i];
    v[4*i+0] = q.x; v[4*i+1] = q.y; v[4*i+2] = q.z; v[4*i+3] = q.w;
  }
}

// ============================================================================
// Phase 1: backward LSTM scan + fused hproj (R5 best, unchanged).
// ============================================================================
__global__ __launch_bounds__(64)
void lstm_bwd_kernel(const float* __restrict__ x,
                     const float* __restrict__ Wih,
                     const float* __restrict__ Whh,
                     const float* __restrict__ bih,
                     const float* __restrict__ bhh,
                     const float* __restrict__ cW1,
                     const float* __restrict__ cb1)
{
  const int l = threadIdx.x & 31;
  const int w = threadIdx.x >> 5;
  const int b = blockIdx.x * 2 + w;
  const int lo = l & 15;

  __shared__ __align__(16) float sH[2][16];
  float* hbuf = sH[w];

  const int r0 = l, r1 = l + 32;
  uint64_t w0[8], w1[8], wHp[8];
  #pragma unroll
  for (int j = 0; j < 8; j++){
    w0[j]  = pk2(Whh[r0*16 + 2*j], Whh[r0*16 + 2*j + 1]);
    w1[j]  = pk2(Whh[r1*16 + 2*j], Whh[r1*16 + 2*j + 1]);
    wHp[j] = pk2(cW1[lo*32 + 2*j], cW1[lo*32 + 2*j + 1]);
  }
  const float wx0 = Wih[r0], wx1 = Wih[r1];
  const float b0 = bih[r0] + bhh[r0];
  const float b1 = bih[r1] + bhh[r1];
  const float bHp = cb1[lo];

  if (l < 16) hbuf[l] = 0.f;
  float c = 0.f;
  __syncwarp();

  const float* xb = x + b;
  float* hpout = g_hproj + (size_t)b * 16 + lo;

  float xt = __ldg(xb + (size_t)(TL-1) * NB);

  for (int t = TL - 1; t >= 0; --t){
    float xn = 0.f;
    if (t > 0) xn = __ldg(xb + (size_t)(t-1) * NB);

    uint64_t hv[8]; ldv8p(hbuf, hv);

    float hp = bHp + dot16p(wHp, hv);
    if (l < 16 && t != TL - 1)
      hpout[(size_t)(t+1) * NB16] = hp;

    float a0 = fmaf(xt, wx0, b0) + dot16p(w0, hv);
    float a1 = fmaf(xt, wx1, b1) + dot16p(w1, hv);

    float p, q = 0.f;
    if (l < 16) { p = sigf(a0) * tanh_fast(a1); }
    else        { p = sigf(a0); q = sigf(a1); }
    float pf = __shfl_xor_sync(FULL, p, 16);
    float qo = __shfl_xor_sync(FULL, q, 16);
    __syncwarp();
    if (l < 16){
      c = fmaf(pf, c, p);
      float hn = qo * tanh_fast(c);
      hbuf[l] = hn;
    }
    __syncwarp();
    xt = xn;
  }

  {
    uint64_t hv[8]; ldv8p(hbuf, hv);
    float hp = bHp + dot16p(wHp, hv);
    if (l < 16) hpout[0] = hp;
  }
}

// ============================================================================
// Phase 2: FUSED DKF + decoder + transition. tr2 & dec1 weights live in
// block-shared memory (conflict-free transposed layouts) to cut register
// pressure below the cap WITHOUT spills. In-reg weights: w1r, w4r, wDr only.
// ============================================================================
#define TS2(j, r) ts2[(j)*33 + (r)]
#define D1S(j, r) d1s[(j)*17 + (r)]

__global__ __launch_bounds__(64, 7)
void dkf_fused_kernel(const float* __restrict__ eps,
                      const float* __restrict__ cW1,
                      const float* __restrict__ cW2, const float* __restrict__ cb2,
                      const float* __restrict__ eW1, const float* __restrict__ eb1,
                      const float* __restrict__ eW2, const float* __restrict__ eb2,
                      const float* __restrict__ dW1, const float* __restrict__ db1,
                      const float* __restrict__ dW2, const float* __restrict__ db2,
                      const float* __restrict__ tW1, const float* __restrict__ tb1,
                      const float* __restrict__ tW2, const float* __restrict__ tb2,
                      float* __restrict__ out)
{
  const int l = threadIdx.x & 31;
  const int w = threadIdx.x >> 5;
  const int b = blockIdx.x * 2 + w;
  const int lo = l & 15;
  const bool low = (l < 16);

  __shared__ __align__(16) float sm[2][80];
  __shared__ float ts2[16*33];   // ts2[j*33+row] = tW2[row*16+j]  (row 0..31)
  __shared__ float d1s[16*17];   // d1s[j*17+row] = dW1[row*16+j]  (row 0..15)
  float* SA = &sm[w][0];    // a1 (16)
  float* ST = &sm[w][16];   // t1 (16)
  float* SD = &sm[w][32];   // d1 (16)
  float* SC = &sm[w][48];   // e1 (16)
  float* SZ = &sm[w][64];   // z  (16)

  // ---- cooperative smem weight fill (block-wide) ----
  for (int idx = threadIdx.x; idx < 512; idx += 64){
    int row = idx >> 4, j = idx & 15;
    TS2(j, row) = tW2[idx];
  }
  for (int idx = threadIdx.x; idx < 256; idx += 64){
    int row = idx >> 4, j = idx & 15;
    D1S(j, row) = dW1[idx];
  }

  // ---- per-lane register weight rows ----
  // w1r: low = cW1 z-cols row lo ; high = tW1 row lo
  uint64_t w1r[8];
  #pragma unroll
  for (int j = 0; j < 8; j++){
    const float* src = low ? (cW1 + lo*32 + 16) : (tW1 + lo*16);
    w1r[j] = pk2(src[2*j], src[2*j+1]);
  }
  // w4r: low = fused M row lo (eW1@cW2); high = dW2 row (l&1)
  uint64_t w4r[8];
  float bM = 0.f;
  if (low){
    float e1w[8];
    #pragma unroll
    for (int k = 0; k < 8; k++) e1w[k] = eW1[lo*8 + k];
    #pragma unroll
    for (int cc = 0; cc < 8; cc++){
      float ax = 0.f, ay = 0.f;
      #pragma unroll
      for (int k = 0; k < 8; k++){
        ax = fmaf(e1w[k], cW2[k*16 + 2*cc],     ax);
        ay = fmaf(e1w[k], cW2[k*16 + 2*cc + 1], ay);
      }
      w4r[cc] = pk2(ax, ay);
    }
    bM = eb1[lo];
    #pragma unroll
    for (int k = 0; k < 8; k++) bM = fmaf(e1w[k], cb2[k], bM);
  } else {
    #pragma unroll
    for (int j = 0; j < 8; j++)
      w4r[j] = pk2(dW2[(l&1)*16 + 2*j], dW2[(l&1)*16 + 2*j + 1]);
  }
  // wDr: enc2 row l
  uint64_t wDr[8];
  #pragma unroll
  for (int j = 0; j < 8; j++)
    wDr[j] = pk2(eW2[l*16 + 2*j], eW2[l*16 + 2*j + 1]);

  const float bT1r = tb1[lo];
  const float bD1r = db1[lo];
  const float bT2r = tb2[l];
  const float bD2r = db2[l & 1];
  const float bDr  = eb2[l];

  if (low) SZ[lo] = 0.f;      // z0
  __syncthreads();            // weights + SZ visible block-wide

  const float* hpp = g_hproj + (size_t)b * 16 + lo;
  const float* epp = eps     + (size_t)b * 16 + lo;
  float*       outp = out    + (size_t)b * 66;

  // ---- 4-deep prefetch ring ----
  float hp0 = __ldg(hpp);
  float hp1 = __ldg(hpp + (size_t)1 * NB16);
  float hp2 = __ldg(hpp + (size_t)2 * NB16);
  float hp3 = __ldg(hpp + (size_t)3 * NB16);
  float ep0 = __ldg(epp);
  float ep1 = __ldg(epp + (size_t)1 * NB16);
  float ep2 = __ldg(epp + (size_t)2 * NB16);
  float ep3 = __ldg(epp + (size_t)3 * NB16);

  #define DKF_STEP(T, HPV, EPSV)                                          \
  {                                                                       \
    /* stage 2: A|tr1 (chain) + dec1 (smem weights, off-chain) */         \
    uint64_t zv[8]; ldv8p(SZ, zv);                                        \
    float base1 = low ? (HPV) : bT1r;                                     \
    float v1 = tanh_fast(base1 + dot16p(w1r, zv));   /* a1 | t1 */        \
    float zb[16]; unpk16(zv, zb);                                         \
    float dA0 = 0.f, dA1 = 0.f, dA2 = 0.f, dA3 = 0.f;                     \
    _Pragma("unroll")                                                     \
    for (int j = 0; j < 16; j += 4){                                      \
      dA0 = fmaf(D1S(j+0, lo), zb[j+0], dA0);                             \
      dA1 = fmaf(D1S(j+1, lo), zb[j+1], dA1);                             \
      dA2 = fmaf(D1S(j+2, lo), zb[j+2], dA2);                             \
      dA3 = fmaf(D1S(j+3, lo), zb[j+3], dA3);                             \
    }                                                                     \
    float d1 = tanh_fast(bD1r + (dA0 + dA1) + (dA2 + dA3));               \
    if (low){ SA[lo] = v1; SD[lo] = d1; } else { ST[lo] = v1; }           \
    __syncwarp();                                                         \
    /* stage 4: tr2 (smem weights) + (e1 | dec2) */                       \
    float tv[16]; ldv16f(ST, tv);                                         \
    float tA0 = 0.f, tA1 = 0.f, tA2 = 0.f, tA3 = 0.f;                     \
    _Pragma("unroll")                                                     \
    for (int j = 0; j < 16; j += 4){                                      \
      tA0 = fmaf(TS2(j+0, l), tv[j+0], tA0);                              \
      tA1 = fmaf(TS2(j+1, l), tv[j+1], tA1);                              \
      tA2 = fmaf(TS2(j+2, l), tv[j+2], tA2);                              \
      tA3 = fmaf(TS2(j+3, l), tv[j+3], tA3);                              \
    }                                                                     \
    outp[34 + l] = bT2r + (tA0 + tA1) + (tA2 + tA3);                      \
    uint64_t av[8]; ldv8p(low ? SA : SD, av);                             \
    float base4 = low ? bM : bD2r;                                        \
    float v4 = base4 + dot16p(w4r, av);              /* e1pre | dx */     \
    if (low) SC[lo] = tanh_fast(v4);                                      \
    else if (((unsigned)(l - 16)) < 2u && (T) > 0)                        \
      (outp - (size_t)NB * 66)[l - 16] = v4;         /* mu_x/logvar_x */  \
    __syncwarp();                                                         \
    /* stage 6: enc2 + sample */                                          \
    uint64_t ev[8]; ldv8p(SC, ev);                                        \
    float e2 = bDr + dot16p(wDr, ev);                                     \
    outp[2 + l] = e2;                                                     \
    float lvz = __shfl_xor_sync(FULL, e2, 16);                            \
    float znew = fmaf((EPSV), __expf(0.5f * lvz), e2);                    \
    if (low) SZ[lo] = znew;                                               \
    __syncwarp();                                                         \
    outp += (size_t)NB * 66;                                              \
  }

  #pragma unroll 1
  for (int t = 0; t < TL; t += 4){
    int t4 = t + 4; if (t4 > TL-1) t4 = TL-1;
    int t5 = t + 5; if (t5 > TL-1) t5 = TL-1;
    int t6 = t + 6; if (t6 > TL-1) t6 = TL-1;
    int t7 = t + 7; if (t7 > TL-1) t7 = TL-1;

    float hpa = __ldg(hpp + (size_t)t4 * NB16);
    float epa = __ldg(epp + (size_t)t4 * NB16);
    DKF_STEP(t + 0, hp0, ep0);
    hp0 = hpa; ep0 = epa;

    float hpb = __ldg(hpp + (size_t)t5 * NB16);
    float epb = __ldg(epp + (size_t)t5 * NB16);
    DKF_STEP(t + 1, hp1, ep1);
    hp1 = hpb; ep1 = epb;

    float hpc = __ldg(hpp + (size_t)t6 * NB16);
    float epc = __ldg(epp + (size_t)t6 * NB16);
    DKF_STEP(t + 2, hp2, ep2);
    hp2 = hpc; ep2 = epc;

    float hpd = __ldg(hpp + (size_t)t7 * NB16);
    float epd = __ldg(epp + (size_t)t7 * NB16);
    DKF_STEP(t + 3, hp3, ep3);
    hp3 = hpd; ep3 = epd;
  }
  #undef DKF_STEP

  // epilogue: decoder for z_{TL-1} (outp now = base + TL*NB*66)
  {
    uint64_t zv[8]; ldv8p(SZ, zv);
    float zb[16]; unpk16(zv, zb);
    float dA0 = 0.f, dA1 = 0.f, dA2 = 0.f, dA3 = 0.f;
    #pragma unroll
    for (int j = 0; j < 16; j += 4){
      dA0 = fmaf(D1S(j+0, lo), zb[j+0], dA0);
      dA1 = fmaf(D1S(j+1, lo), zb[j+1], dA1);
      dA2 = fmaf(D1S(j+2, lo), zb[j+2], dA2);
      dA3 = fmaf(D1S(j+3, lo), zb[j+3], dA3);
    }
    float d1 = tanh_fast(bD1r + (dA0 + dA1) + (dA2 + dA3));
    if (low) SD[lo] = d1;
    __syncwarp();
    uint64_t dv[8]; ldv8p(SD, dv);
    float dx = bD2r + dot16p(w4r, dv);     // valid on high lanes
    if (((unsigned)(l - 16)) < 2u)
      (outp - (size_t)NB * 66)[l - 16] = dx;
  }
}

extern "C" void kernel_launch(void* const* d_in, const int* in_sizes, int n_in,
                              void* d_out, int out_size)
{
  const float* x   = (const float*)d_in[0];
  const float* eps = (const float*)d_in[1];
  const float* Wih = (const float*)d_in[2];
  const float* Whh = (const float*)d_in[3];
  const float* bih = (const float*)d_in[4];
  const float* bhh = (const float*)d_in[5];
  const float* cW1 = (const float*)d_in[6];
  const float* cb1 = (const float*)d_in[7];
  const float* cW2 = (const float*)d_in[8];
  const float* cb2 = (const float*)d_in[9];
  const float* eW1 = (const float*)d_in[10];
  const float* eb1 = (const float*)d_in[11];
  const float* eW2 = (const float*)d_in[12];
  const float* eb2 = (const float*)d_in[13];
  const float* dW1 = (const float*)d_in[14];
  const float* db1 = (const float*)d_in[15];
  const float* dW2 = (const float*)d_in[16];
  const float* db2 = (const float*)d_in[17];
  const float* tW1 = (const float*)d_in[18];
  const float* tb1 = (const float*)d_in[19];
  const float* tW2 = (const float*)d_in[20];
  const float* tb2 = (const float*)d_in[21];
  float* out = (float*)d_out;

  lstm_bwd_kernel<<<NB/2, 64>>>(x, Wih, Whh, bih, bhh, cW1, cb1);
  dkf_fused_kernel<<<NB/2, 64>>>(eps, cW1, cW2, cb2, eW1, eb1, eW2, eb2,
                                 dW1, db1, dW2, db2, tW1, tb1, tW2, tb2, out);
}

// round 14
// speedup vs baseline: 1.2295x; 1.0547x over previous
#include <cuda_runtime.h>
#include <cstdint>
#include <cstddef>

#define TL 512
#define NB 2048
#define NB16 (NB*16)
#define FULL 0xffffffffu

// scratch: hproj_seq, T*B*16 floats = 64 MiB
__device__ float g_hproj[(size_t)TL * NB * 16];

__device__ __forceinline__ float sigf(float x){
  return __fdividef(1.f, 1.f + __expf(-x));
}
__device__ __forceinline__ float tanh_fast(float x){
  return __fdividef(2.f, 1.f + __expf(-2.f * x)) - 1.f;
}

// ---- packed f32x2 helpers ----
__device__ __forceinline__ uint64_t pk2(float lo, float hi){
  uint64_t r; asm("mov.b64 %0, {%1, %2};" : "=l"(r) : "f"(lo), "f"(hi)); return r;
}
__device__ __forceinline__ uint64_t fma2(uint64_t a, uint64_t b, uint64_t c){
  uint64_t d; asm("fma.rn.f32x2 %0, %1, %2, %3;" : "=l"(d) : "l"(a), "l"(b), "l"(c));
  return d;
}
__device__ __forceinline__ float dot16p(const uint64_t w[8], const uint64_t v[8]){
  const uint64_t z = 0;
  uint64_t a0 = fma2(w[0], v[0], z);
  uint64_t a1 = fma2(w[1], v[1], z);
  a0 = fma2(w[2], v[2], a0);
  a1 = fma2(w[3], v[3], a1);
  a0 = fma2(w[4], v[4], a0);
  a1 = fma2(w[5], v[5], a1);
  a0 = fma2(w[6], v[6], a0);
  a1 = fma2(w[7], v[7], a1);
  uint64_t s; asm("add.rn.f32x2 %0, %1, %2;" : "=l"(s) : "l"(a0), "l"(a1));
  float lo, hi; asm("mov.b64 {%0, %1}, %2;" : "=f"(lo), "=f"(hi) : "l"(s));
  return lo + hi;
}
__device__ __forceinline__ void ldv8p(const float* p, uint64_t v[8]){
  #pragma unroll
  for (int i = 0; i < 4; i++){
    ulonglong2 q = reinterpret_cast<const ulonglong2*>(p)[i];
    v[2*i] = q.x; v[2*i+1] = q.y;
  }
}
__device__ __forceinline__ void unpk16(const uint64_t v[8], float s[16]){
  #pragma unroll
  for (int i = 0; i < 8; i++)
    asm("mov.b64 {%0, %1}, %2;" : "=f"(s[2*i]), "=f"(s[2*i+1]) : "l"(v[i]));
}
__device__ __forceinline__ void ldv16f(const float* p, float v[16]){
  #pragma unroll
  for (int i = 0; i < 4; i++){
    float4 q = reinterpret_cast<const float4*>(p)[i];
    v[4*i+0] = q.x; v[4*i+1] = q.y; v[4*i+2] = q.z; v[4*i+3] = q.w;
  }
}
// dot of 4 float4 weight chunks against 16 scalars
__device__ __forceinline__ float dotq16(const float4 q[4], const float v[16]){
  float a0 = 0.f, a1 = 0.f, a2 = 0.f, a3 = 0.f;
  #pragma unroll
  for (int j = 0; j < 4; j++){
    a0 = fmaf(q[j].x, v[4*j+0], a0);
    a1 = fmaf(q[j].y, v[4*j+1], a1);
    a2 = fmaf(q[j].z, v[4*j+2], a2);
    a3 = fmaf(q[j].w, v[4*j+3], a3);
  }
  return (a0 + a1) + (a2 + a3);
}

// ============================================================================
// Phase 1: backward LSTM scan + fused hproj (R5 best, unchanged).
// ============================================================================
__global__ __launch_bounds__(64)
void lstm_bwd_kernel(const float* __restrict__ x,
                     const float* __restrict__ Wih,
                     const float* __restrict__ Whh,
                     const float* __restrict__ bih,
                     const float* __restrict__ bhh,
                     const float* __restrict__ cW1,
                     const float* __restrict__ cb1)
{
  const int l = threadIdx.x & 31;
  const int w = threadIdx.x >> 5;
  const int b = blockIdx.x * 2 + w;
  const int lo = l & 15;

  __shared__ __align__(16) float sH[2][16];
  float* hbuf = sH[w];

  const int r0 = l, r1 = l + 32;
  uint64_t w0[8], w1[8], wHp[8];
  #pragma unroll
  for (int j = 0; j < 8; j++){
    w0[j]  = pk2(Whh[r0*16 + 2*j], Whh[r0*16 + 2*j + 1]);
    w1[j]  = pk2(Whh[r1*16 + 2*j], Whh[r1*16 + 2*j + 1]);
    wHp[j] = pk2(cW1[lo*32 + 2*j], cW1[lo*32 + 2*j + 1]);
  }
  const float wx0 = Wih[r0], wx1 = Wih[r1];
  const float b0 = bih[r0] + bhh[r0];
  const float b1 = bih[r1] + bhh[r1];
  const float bHp = cb1[lo];

  if (l < 16) hbuf[l] = 0.f;
  float c = 0.f;
  __syncwarp();

  const float* xb = x + b;
  float* hpout = g_hproj + (size_t)b * 16 + lo;

  float xt = __ldg(xb + (size_t)(TL-1) * NB);

  for (int t = TL - 1; t >= 0; --t){
    float xn = 0.f;
    if (t > 0) xn = __ldg(xb + (size_t)(t-1) * NB);

    uint64_t hv[8]; ldv8p(hbuf, hv);

    float hp = bHp + dot16p(wHp, hv);
    if (l < 16 && t != TL - 1)
      hpout[(size_t)(t+1) * NB16] = hp;

    float a0 = fmaf(xt, wx0, b0) + dot16p(w0, hv);
    float a1 = fmaf(xt, wx1, b1) + dot16p(w1, hv);

    float p, q = 0.f;
    if (l < 16) { p = sigf(a0) * tanh_fast(a1); }
    else        { p = sigf(a0); q = sigf(a1); }
    float pf = __shfl_xor_sync(FULL, p, 16);
    float qo = __shfl_xor_sync(FULL, q, 16);
    __syncwarp();
    if (l < 16){
      c = fmaf(pf, c, p);
      float hn = qo * tanh_fast(c);
      hbuf[l] = hn;
    }
    __syncwarp();
    xt = xn;
  }

  {
    uint64_t hv[8]; ldv8p(hbuf, hv);
    float hp = bHp + dot16p(wHp, hv);
    if (l < 16) hpout[0] = hp;
  }
}

// ============================================================================
// Phase 2: FUSED DKF + decoder + transition. tr2 & dec1 weights in smem as
// float4 rows with stride-5 padding (conflict-free LDS.128):
//   ts2q[l*5 + jj]  = tW2 row l, chunk jj   (32 rows)
//   d1q [lo*5 + jj] = dW1 row lo, chunk jj  (16 rows; broadcast across halves)
// 8 LDS.128 per step replace R13's 32 scalar LDS.
// ============================================================================
__global__ __launch_bounds__(64, 7)
void dkf_fused_kernel(const float* __restrict__ eps,
                      const float* __restrict__ cW1,
                      const float* __restrict__ cW2, const float* __restrict__ cb2,
                      const float* __restrict__ eW1, const float* __restrict__ eb1,
                      const float* __restrict__ eW2, const float* __restrict__ eb2,
                      const float* __restrict__ dW1, const float* __restrict__ db1,
                      const float* __restrict__ dW2, const float* __restrict__ db2,
                      const float* __restrict__ tW1, const float* __restrict__ tb1,
                      const float* __restrict__ tW2, const float* __restrict__ tb2,
                      float* __restrict__ out)
{
  const int l = threadIdx.x & 31;
  const int w = threadIdx.x >> 5;
  const int b = blockIdx.x * 2 + w;
  const int lo = l & 15;
  const bool low = (l < 16);

  __shared__ __align__(16) float sm[2][80];
  __shared__ __align__(16) float4 ts2q[32*5];   // tr2 rows, stride 5
  __shared__ __align__(16) float4 d1q[16*5];    // dec1 rows, stride 5
  float* SA = &sm[w][0];    // a1 (16)
  float* ST = &sm[w][16];   // t1 (16)
  float* SD = &sm[w][32];   // d1 (16)
  float* SC = &sm[w][48];   // e1 (16)
  float* SZ = &sm[w][64];   // z  (16)

  // ---- cooperative smem weight fill (block-wide) ----
  {
    const float4* t4 = reinterpret_cast<const float4*>(tW2);   // 128 float4
    for (int idx = threadIdx.x; idx < 128; idx += 64)
      ts2q[(idx >> 2) * 5 + (idx & 3)] = t4[idx];
    const float4* d4 = reinterpret_cast<const float4*>(dW1);   // 64 float4
    if (threadIdx.x < 64){
      int idx = threadIdx.x;
      d1q[(idx >> 2) * 5 + (idx & 3)] = d4[idx];
    }
  }

  // ---- per-lane register weight rows ----
  // w1r: low = cW1 z-cols row lo ; high = tW1 row lo
  uint64_t w1r[8];
  #pragma unroll
  for (int j = 0; j < 8; j++){
    const float* src = low ? (cW1 + lo*32 + 16) : (tW1 + lo*16);
    w1r[j] = pk2(src[2*j], src[2*j+1]);
  }
  // w4r: low = fused M row lo (eW1@cW2); high = dW2 row (l&1)
  uint64_t w4r[8];
  float bM = 0.f;
  if (low){
    float e1w[8];
    #pragma unroll
    for (int k = 0; k < 8; k++) e1w[k] = eW1[lo*8 + k];
    #pragma unroll
    for (int cc = 0; cc < 8; cc++){
      float ax = 0.f, ay = 0.f;
      #pragma unroll
      for (int k = 0; k < 8; k++){
        ax = fmaf(e1w[k], cW2[k*16 + 2*cc],     ax);
        ay = fmaf(e1w[k], cW2[k*16 + 2*cc + 1], ay);
      }
      w4r[cc] = pk2(ax, ay);
    }
    bM = eb1[lo];
    #pragma unroll
    for (int k = 0; k < 8; k++) bM = fmaf(e1w[k], cb2[k], bM);
  } else {
    #pragma unroll
    for (int j = 0; j < 8; j++)
      w4r[j] = pk2(dW2[(l&1)*16 + 2*j], dW2[(l&1)*16 + 2*j + 1]);
  }
  // wDr: enc2 row l
  uint64_t wDr[8];
  #pragma unroll
  for (int j = 0; j < 8; j++)
    wDr[j] = pk2(eW2[l*16 + 2*j], eW2[l*16 + 2*j + 1]);

  const float bT1r = tb1[lo];
  const float bD1r = db1[lo];
  const float bT2r = tb2[l];
  const float bD2r = db2[l & 1];
  const float bDr  = eb2[l];

  if (low) SZ[lo] = 0.f;      // z0
  __syncthreads();            // weights + SZ visible block-wide

  const float* hpp = g_hproj + (size_t)b * 16 + lo;
  const float* epp = eps     + (size_t)b * 16 + lo;
  float*       outp = out    + (size_t)b * 66;

  // ---- 4-deep prefetch ring ----
  float hp0 = __ldg(hpp);
  float hp1 = __ldg(hpp + (size_t)1 * NB16);
  float hp2 = __ldg(hpp + (size_t)2 * NB16);
  float hp3 = __ldg(hpp + (size_t)3 * NB16);
  float ep0 = __ldg(epp);
  float ep1 = __ldg(epp + (size_t)1 * NB16);
  float ep2 = __ldg(epp + (size_t)2 * NB16);
  float ep3 = __ldg(epp + (size_t)3 * NB16);

  #define DKF_STEP(T, HPV, EPSV)                                          \
  {                                                                       \
    /* stage 2: A|tr1 (chain) + dec1 (float4 smem weights, off-chain) */  \
    uint64_t zv[8]; ldv8p(SZ, zv);                                        \
    float base1 = low ? (HPV) : bT1r;                                     \
    float v1 = tanh_fast(base1 + dot16p(w1r, zv));   /* a1 | t1 */        \
    float zb[16]; unpk16(zv, zb);                                         \
    float4 dq[4];                                                         \
    _Pragma("unroll")                                                     \
    for (int jj = 0; jj < 4; jj++) dq[jj] = d1q[lo*5 + jj];               \
    float d1 = tanh_fast(bD1r + dotq16(dq, zb));                          \
    if (low){ SA[lo] = v1; SD[lo] = d1; } else { ST[lo] = v1; }           \
    __syncwarp();                                                         \
    /* stage 4: tr2 (float4 smem weights) + (e1 | dec2) */                \
    float tv[16]; ldv16f(ST, tv);                                         \
    float4 tq[4];                                                         \
    _Pragma("unroll")                                                     \
    for (int jj = 0; jj < 4; jj++) tq[jj] = ts2q[l*5 + jj];               \
    outp[34 + l] = bT2r + dotq16(tq, tv);                                 \
    uint64_t av[8]; ldv8p(low ? SA : SD, av);                             \
    float base4 = low ? bM : bD2r;                                        \
    float v4 = base4 + dot16p(w4r, av);              /* e1pre | dx */     \
    if (low) SC[lo] = tanh_fast(v4);                                      \
    else if (((unsigned)(l - 16)) < 2u && (T) > 0)                        \
      (outp - (size_t)NB * 66)[l - 16] = v4;         /* mu_x/logvar_x */  \
    __syncwarp();                                                         \
    /* stage 6: enc2 + sample */                                          \
    uint64_t ev[8]; ldv8p(SC, ev);                                        \
    float e2 = bDr + dot16p(wDr, ev);                                     \
    outp[2 + l] = e2;                                                     \
    float lvz = __shfl_xor_sync(FULL, e2, 16);                            \
    float znew = fmaf((EPSV), __expf(0.5f * lvz), e2);                    \
    if (low) SZ[lo] = znew;                                               \
    __syncwarp();                                                         \
    outp += (size_t)NB * 66;                                              \
  }

  #pragma unroll 1
  for (int t = 0; t < TL; t += 4){
    int t4 = t + 4; if (t4 > TL-1) t4 = TL-1;
    int t5 = t + 5; if (t5 > TL-1) t5 = TL-1;
    int t6 = t + 6; if (t6 > TL-1) t6 = TL-1;
    int t7 = t + 7; if (t7 > TL-1) t7 = TL-1;

    float hpa = __ldg(hpp + (size_t)t4 * NB16);
    float epa = __ldg(epp + (size_t)t4 * NB16);
    DKF_STEP(t + 0, hp0, ep0);
    hp0 = hpa; ep0 = epa;

    float hpb = __ldg(hpp + (size_t)t5 * NB16);
    float epb = __ldg(epp + (size_t)t5 * NB16);
    DKF_STEP(t + 1, hp1, ep1);
    hp1 = hpb; ep1 = epb;

    float hpc = __ldg(hpp + (size_t)t6 * NB16);
    float epc = __ldg(epp + (size_t)t6 * NB16);
    DKF_STEP(t + 2, hp2, ep2);
    hp2 = hpc; ep2 = epc;

    float hpd = __ldg(hpp + (size_t)t7 * NB16);
    float epd = __ldg(epp + (size_t)t7 * NB16);
    DKF_STEP(t + 3, hp3, ep3);
    hp3 = hpd; ep3 = epd;
  }
  #undef DKF_STEP

  // epilogue: decoder for z_{TL-1} (outp now = base + TL*NB*66)
  {
    uint64_t zv[8]; ldv8p(SZ, zv);
    float zb[16]; unpk16(zv, zb);
    float4 dq[4];
    #pragma unroll
    for (int jj = 0; jj < 4; jj++) dq[jj] = d1q[lo*5 + jj];
    float d1 = tanh_fast(bD1r + dotq16(dq, zb));
    if (low) SD[lo] = d1;
    __syncwarp();
    uint64_t dv[8]; ldv8p(SD, dv);
    float dx = bD2r + dot16p(w4r, dv);     // valid on high lanes
    if (((unsigned)(l - 16)) < 2u)
      (outp - (size_t)NB * 66)[l - 16] = dx;
  }
}

extern "C" void kernel_launch(void* const* d_in, const int* in_sizes, int n_in,
                              void* d_out, int out_size)
{
  const float* x   = (const float*)d_in[0];
  const float* eps = (const float*)d_in[1];
  const float* Wih = (const float*)d_in[2];
  const float* Whh = (const float*)d_in[3];
  const float* bih = (const float*)d_in[4];
  const float* bhh = (const float*)d_in[5];
  const float* cW1 = (const float*)d_in[6];
  const float* cb1 = (const float*)d_in[7];
  const float* cW2 = (const float*)d_in[8];
  const float* cb2 = (const float*)d_in[9];
  const float* eW1 = (const float*)d_in[10];
  const float* eb1 = (const float*)d_in[11];
  const float* eW2 = (const float*)d_in[12];
  const float* eb2 = (const float*)d_in[13];
  const float* dW1 = (const float*)d_in[14];
  const float* db1 = (const float*)d_in[15];
  const float* dW2 = (const float*)d_in[16];
  const float* db2 = (const float*)d_in[17];
  const float* tW1 = (const float*)d_in[18];
  const float* tb1 = (const float*)d_in[19];
  const float* tW2 = (const float*)d_in[20];
  const float* tb2 = (const float*)d_in[21];
  float* out = (float*)d_out;

  lstm_bwd_kernel<<<NB/2, 64>>>(x, Wih, Whh, bih, bhh, cW1, cb1);
  dkf_fused_kernel<<<NB/2, 64>>>(eps, cW1, cW2, cb2, eW1, eb1, eW2, eb2,
                                 dW1, db1, dW2, db2, tW1, tb1, tW2, tb2, out);
}

// round 15
// speedup vs baseline: 1.2521x; 1.0184x over previous
#include <cuda_runtime.h>
#include <cstdint>
#include <cstddef>

#define TL 512
#define NB 2048
#define NB16 (NB*16)
#define FULL 0xffffffffu

// scratch: hproj_seq, T*B*16 floats = 64 MiB
__device__ float g_hproj[(size_t)TL * NB * 16];

__device__ __forceinline__ float sigf(float x){
  return __fdividef(1.f, 1.f + __expf(-x));
}
__device__ __forceinline__ float tanh_fast(float x){
  return __fdividef(2.f, 1.f + __expf(-2.f * x)) - 1.f;
}

// ---- packed f32x2 helpers ----
__device__ __forceinline__ uint64_t pk2(float lo, float hi){
  uint64_t r; asm("mov.b64 %0, {%1, %2};" : "=l"(r) : "f"(lo), "f"(hi)); return r;
}
__device__ __forceinline__ uint64_t fma2(uint64_t a, uint64_t b, uint64_t c){
  uint64_t d; asm("fma.rn.f32x2 %0, %1, %2, %3;" : "=l"(d) : "l"(a), "l"(b), "l"(c));
  return d;
}
__device__ __forceinline__ float dot16p(const uint64_t w[8], const uint64_t v[8]){
  const uint64_t z = 0;
  uint64_t a0 = fma2(w[0], v[0], z);
  uint64_t a1 = fma2(w[1], v[1], z);
  a0 = fma2(w[2], v[2], a0);
  a1 = fma2(w[3], v[3], a1);
  a0 = fma2(w[4], v[4], a0);
  a1 = fma2(w[5], v[5], a1);
  a0 = fma2(w[6], v[6], a0);
  a1 = fma2(w[7], v[7], a1);
  uint64_t s; asm("add.rn.f32x2 %0, %1, %2;" : "=l"(s) : "l"(a0), "l"(a1));
  float lo, hi; asm("mov.b64 {%0, %1}, %2;" : "=f"(lo), "=f"(hi) : "l"(s));
  return lo + hi;
}
__device__ __forceinline__ void ldv8p(const float* p, uint64_t v[8]){
  #pragma unroll
  for (int i = 0; i < 4; i++){
    ulonglong2 q = reinterpret_cast<const ulonglong2*>(p)[i];
    v[2*i] = q.x; v[2*i+1] = q.y;
  }
}
__device__ __forceinline__ void unpk16(const uint64_t v[8], float s[16]){
  #pragma unroll
  for (int i = 0; i < 8; i++)
    asm("mov.b64 {%0, %1}, %2;" : "=f"(s[2*i]), "=f"(s[2*i+1]) : "l"(v[i]));
}
// dot of 4 float4 weight chunks against 16 scalars
__device__ __forceinline__ float dotq16(const float4 q[4], const float v[16]){
  float a0 = 0.f, a1 = 0.f, a2 = 0.f, a3 = 0.f;
  #pragma unroll
  for (int j = 0; j < 4; j++){
    a0 = fmaf(q[j].x, v[4*j+0], a0);
    a1 = fmaf(q[j].y, v[4*j+1], a1);
    a2 = fmaf(q[j].z, v[4*j+2], a2);
    a3 = fmaf(q[j].w, v[4*j+3], a3);
  }
  return (a0 + a1) + (a2 + a3);
}

// ============================================================================
// Phase 1: backward LSTM scan + fused hproj (R5 best, unchanged).
// ============================================================================
__global__ __launch_bounds__(64)
void lstm_bwd_kernel(const float* __restrict__ x,
                     const float* __restrict__ Wih,
                     const float* __restrict__ Whh,
                     const float* __restrict__ bih,
                     const float* __restrict__ bhh,
                     const float* __restrict__ cW1,
                     const float* __restrict__ cb1)
{
  const int l = threadIdx.x & 31;
  const int w = threadIdx.x >> 5;
  const int b = blockIdx.x * 2 + w;
  const int lo = l & 15;

  __shared__ __align__(16) float sH[2][16];
  float* hbuf = sH[w];

  const int r0 = l, r1 = l + 32;
  uint64_t w0[8], w1[8], wHp[8];
  #pragma unroll
  for (int j = 0; j < 8; j++){
    w0[j]  = pk2(Whh[r0*16 + 2*j], Whh[r0*16 + 2*j + 1]);
    w1[j]  = pk2(Whh[r1*16 + 2*j], Whh[r1*16 + 2*j + 1]);
    wHp[j] = pk2(cW1[lo*32 + 2*j], cW1[lo*32 + 2*j + 1]);
  }
  const float wx0 = Wih[r0], wx1 = Wih[r1];
  const float b0 = bih[r0] + bhh[r0];
  const float b1 = bih[r1] + bhh[r1];
  const float bHp = cb1[lo];

  if (l < 16) hbuf[l] = 0.f;
  float c = 0.f;
  __syncwarp();

  const float* xb = x + b;
  float* hpout = g_hproj + (size_t)b * 16 + lo;

  float xt = __ldg(xb + (size_t)(TL-1) * NB);

  for (int t = TL - 1; t >= 0; --t){
    float xn = 0.f;
    if (t > 0) xn = __ldg(xb + (size_t)(t-1) * NB);

    uint64_t hv[8]; ldv8p(hbuf, hv);

    float hp = bHp + dot16p(wHp, hv);
    if (l < 16 && t != TL - 1)
      hpout[(size_t)(t+1) * NB16] = hp;

    float a0 = fmaf(xt, wx0, b0) + dot16p(w0, hv);
    float a1 = fmaf(xt, wx1, b1) + dot16p(w1, hv);

    float p, q = 0.f;
    if (l < 16) { p = sigf(a0) * tanh_fast(a1); }
    else        { p = sigf(a0); q = sigf(a1); }
    float pf = __shfl_xor_sync(FULL, p, 16);
    float qo = __shfl_xor_sync(FULL, q, 16);
    __syncwarp();
    if (l < 16){
      c = fmaf(pf, c, p);
      float hn = qo * tanh_fast(c);
      hbuf[l] = hn;
    }
    __syncwarp();
    xt = xn;
  }

  {
    uint64_t hv[8]; ldv8p(hbuf, hv);
    float hp = bHp + dot16p(wHp, hv);
    if (l < 16) hpout[0] = hp;
  }
}

// ============================================================================
// Phase 2: FUSED DKF + decoder + transition.
// tr2 weights BACK IN REGISTERS (w3r; 128+16=144 <= 146 cap, still 7 blk/SM,
// single wave). dec1 stays in smem float4 (stride-5, conflict-free).
// Removes the 16 heaviest LSU wavefronts per step (tr2 weight LDS).
// ============================================================================
__global__ __launch_bounds__(64, 7)
void dkf_fused_kernel(const float* __restrict__ eps,
                      const float* __restrict__ cW1,
                      const float* __restrict__ cW2, const float* __restrict__ cb2,
                      const float* __restrict__ eW1, const float* __restrict__ eb1,
                      const float* __restrict__ eW2, const float* __restrict__ eb2,
                      const float* __restrict__ dW1, const float* __restrict__ db1,
                      const float* __restrict__ dW2, const float* __restrict__ db2,
                      const float* __restrict__ tW1, const float* __restrict__ tb1,
                      const float* __restrict__ tW2, const float* __restrict__ tb2,
                      float* __restrict__ out)
{
  const int l = threadIdx.x & 31;
  const int w = threadIdx.x >> 5;
  const int b = blockIdx.x * 2 + w;
  const int lo = l & 15;
  const bool low = (l < 16);

  __shared__ __align__(16) float sm[2][80];
  __shared__ __align__(16) float4 d1q[16*5];    // dec1 rows, stride 5
  float* SA = &sm[w][0];    // a1 (16)
  float* ST = &sm[w][16];   // t1 (16)
  float* SD = &sm[w][32];   // d1 (16)
  float* SC = &sm[w][48];   // e1 (16)
  float* SZ = &sm[w][64];   // z  (16)

  // ---- cooperative smem weight fill (block-wide) ----
  {
    const float4* d4 = reinterpret_cast<const float4*>(dW1);   // 64 float4
    if (threadIdx.x < 64){
      int idx = threadIdx.x;
      d1q[(idx >> 2) * 5 + (idx & 3)] = d4[idx];
    }
  }

  // ---- per-lane register weight rows ----
  // w1r: low = cW1 z-cols row lo ; high = tW1 row lo
  uint64_t w1r[8];
  #pragma unroll
  for (int j = 0; j < 8; j++){
    const float* src = low ? (cW1 + lo*32 + 16) : (tW1 + lo*16);
    w1r[j] = pk2(src[2*j], src[2*j+1]);
  }
  // w3r: tr2 row l (all lanes)
  uint64_t w3r[8];
  #pragma unroll
  for (int j = 0; j < 8; j++)
    w3r[j] = pk2(tW2[l*16 + 2*j], tW2[l*16 + 2*j + 1]);
  // w4r: low = fused M row lo (eW1@cW2); high = dW2 row (l&1)
  uint64_t w4r[8];
  float bM = 0.f;
  if (low){
    float e1w[8];
    #pragma unroll
    for (int k = 0; k < 8; k++) e1w[k] = eW1[lo*8 + k];
    #pragma unroll
    for (int cc = 0; cc < 8; cc++){
      float ax = 0.f, ay = 0.f;
      #pragma unroll
      for (int k = 0; k < 8; k++){
        ax = fmaf(e1w[k], cW2[k*16 + 2*cc],     ax);
        ay = fmaf(e1w[k], cW2[k*16 + 2*cc + 1], ay);
      }
      w4r[cc] = pk2(ax, ay);
    }
    bM = eb1[lo];
    #pragma unroll
    for (int k = 0; k < 8; k++) bM = fmaf(e1w[k], cb2[k], bM);
  } else {
    #pragma unroll
    for (int j = 0; j < 8; j++)
      w4r[j] = pk2(dW2[(l&1)*16 + 2*j], dW2[(l&1)*16 + 2*j + 1]);
  }
  // wDr: enc2 row l
  uint64_t wDr[8];
  #pragma unroll
  for (int j = 0; j < 8; j++)
    wDr[j] = pk2(eW2[l*16 + 2*j], eW2[l*16 + 2*j + 1]);

  const float bT1r = tb1[lo];
  const float bD1r = db1[lo];
  const float bT2r = tb2[l];
  const float bD2r = db2[l & 1];
  const float bDr  = eb2[l];

  if (low) SZ[lo] = 0.f;      // z0
  __syncthreads();            // weights + SZ visible block-wide

  const float* hpp = g_hproj + (size_t)b * 16 + lo;
  const float* epp = eps     + (size_t)b * 16 + lo;
  float*       outp = out    + (size_t)b * 66;

  // ---- 4-deep prefetch ring ----
  float hp0 = __ldg(hpp);
  float hp1 = __ldg(hpp + (size_t)1 * NB16);
  float hp2 = __ldg(hpp + (size_t)2 * NB16);
  float hp3 = __ldg(hpp + (size_t)3 * NB16);
  float ep0 = __ldg(epp);
  float ep1 = __ldg(epp + (size_t)1 * NB16);
  float ep2 = __ldg(epp + (size_t)2 * NB16);
  float ep3 = __ldg(epp + (size_t)3 * NB16);

  #define DKF_STEP(T, HPV, EPSV)                                          \
  {                                                                       \
    /* stage 2: A|tr1 (chain) + dec1 (float4 smem weights, off-chain) */  \
    uint64_t zv[8]; ldv8p(SZ, zv);                                        \
    float base1 = low ? (HPV) : bT1r;                                     \
    float v1 = tanh_fast(base1 + dot16p(w1r, zv));   /* a1 | t1 */        \
    float zb[16]; unpk16(zv, zb);                                         \
    float4 dq[4];                                                         \
    _Pragma("unroll")                                                     \
    for (int jj = 0; jj < 4; jj++) dq[jj] = d1q[lo*5 + jj];               \
    float d1 = tanh_fast(bD1r + dotq16(dq, zb));                          \
    if (low){ SA[lo] = v1; SD[lo] = d1; } else { ST[lo] = v1; }           \
    __syncwarp();                                                         \
    /* stage 4: tr2 (register weights) + (e1 | dec2) */                   \
    uint64_t tv[8]; ldv8p(ST, tv);                                        \
    outp[34 + l] = bT2r + dot16p(w3r, tv);                                \
    uint64_t av[8]; ldv8p(low ? SA : SD, av);                             \
    float base4 = low ? bM : bD2r;                                        \
    float v4 = base4 + dot16p(w4r, av);              /* e1pre | dx */     \
    if (low) SC[lo] = tanh_fast(v4);                                      \
    else if (((unsigned)(l - 16)) < 2u && (T) > 0)                        \
      (outp - (size_t)NB * 66)[l - 16] = v4;         /* mu_x/logvar_x */  \
    __syncwarp();                                                         \
    /* stage 6: enc2 + sample */                                          \
    uint64_t ev[8]; ldv8p(SC, ev);                                        \
    float e2 = bDr + dot16p(wDr, ev);                                     \
    outp[2 + l] = e2;                                                     \
    float lvz = __shfl_xor_sync(FULL, e2, 16);                            \
    float znew = fmaf((EPSV), __expf(0.5f * lvz), e2);                    \
    if (low) SZ[lo] = znew;                                               \
    __syncwarp();                                                         \
    outp += (size_t)NB * 66;                                              \
  }

  #pragma unroll 1
  for (int t = 0; t < TL; t += 4){
    int t4 = t + 4; if (t4 > TL-1) t4 = TL-1;
    int t5 = t + 5; if (t5 > TL-1) t5 = TL-1;
    int t6 = t + 6; if (t6 > TL-1) t6 = TL-1;
    int t7 = t + 7; if (t7 > TL-1) t7 = TL-1;

    float hpa = __ldg(hpp + (size_t)t4 * NB16);
    float epa = __ldg(epp + (size_t)t4 * NB16);
    DKF_STEP(t + 0, hp0, ep0);
    hp0 = hpa; ep0 = epa;

    float hpb = __ldg(hpp + (size_t)t5 * NB16);
    float epb = __ldg(epp + (size_t)t5 * NB16);
    DKF_STEP(t + 1, hp1, ep1);
    hp1 = hpb; ep1 = epb;

    float hpc = __ldg(hpp + (size_t)t6 * NB16);
    float epc = __ldg(epp + (size_t)t6 * NB16);
    DKF_STEP(t + 2, hp2, ep2);
    hp2 = hpc; ep2 = epc;

    float hpd = __ldg(hpp + (size_t)t7 * NB16);
    float epd = __ldg(epp + (size_t)t7 * NB16);
    DKF_STEP(t + 3, hp3, ep3);
    hp3 = hpd; ep3 = epd;
  }
  #undef DKF_STEP

  // epilogue: decoder for z_{TL-1} (outp now = base + TL*NB*66)
  {
    uint64_t zv[8]; ldv8p(SZ, zv);
    float zb[16]; unpk16(zv, zb);
    float4 dq[4];
    #pragma unroll
    for (int jj = 0; jj < 4; jj++) dq[jj] = d1q[lo*5 + jj];
    float d1 = tanh_fast(bD1r + dotq16(dq, zb));
    if (low) SD[lo] = d1;
    __syncwarp();
    uint64_t dv[8]; ldv8p(SD, dv);
    float dx = bD2r + dot16p(w4r, dv);     // valid on high lanes
    if (((unsigned)(l - 16)) < 2u)
      (outp - (size_t)NB * 66)[l - 16] = dx;
  }
}

extern "C" void kernel_launch(void* const* d_in, const int* in_sizes, int n_in,
                              void* d_out, int out_size)
{
  const float* x   = (const float*)d_in[0];
  const float* eps = (const float*)d_in[1];
  const float* Wih = (const float*)d_in[2];
  const float* Whh = (const float*)d_in[3];
  const float* bih = (const float*)d_in[4];
  const float* bhh = (const float*)d_in[5];
  const float* cW1 = (const float*)d_in[6];
  const float* cb1 = (const float*)d_in[7];
  const float* cW2 = (const float*)d_in[8];
  const float* cb2 = (const float*)d_in[9];
  const float* eW1 = (const float*)d_in[10];
  const float* eb1 = (const float*)d_in[11];
  const float* eW2 = (const float*)d_in[12];
  const float* eb2 = (const float*)d_in[13];
  const float* dW1 = (const float*)d_in[14];
  const float* db1 = (const float*)d_in[15];
  const float* dW2 = (const float*)d_in[16];
  const float* db2 = (const float*)d_in[17];
  const float* tW1 = (const float*)d_in[18];
  const float* tb1 = (const float*)d_in[19];
  const float* tW2 = (const float*)d_in[20];
  const float* tb2 = (const float*)d_in[21];
  float* out = (float*)d_out;

  lstm_bwd_kernel<<<NB/2, 64>>>(x, Wih, Whh, bih, bhh, cW1, cb1);
  dkf_fused_kernel<<<NB/2, 64>>>(eps, cW1, cW2, cb2, eW1, eb1, eW2, eb2,
                                 dW1, db1, dW2, db2, tW1, tb1, tW2, tb2, out);
}